// round 9
// baseline (speedup 1.0000x reference)
#include <cuda_runtime.h>
#include <math.h>

#define B_  32
#define T_  2048
#define D_  512
#define H_  512
#define G4_ 2048   // 4*H

// ---------------- device scratch ----------------
__device__ float g_xp[(size_t)B_ * T_ * G4_];   // x_proj scratch [B][T][4H]
__device__ float g_h[2][B_ * H_];               // double-buffered hidden state
__device__ unsigned int g_ctr4[4 * 32];         // per-batch-group counters (128B apart)
__device__ unsigned int g_epoch4[4 * 32];       // per-batch-group epoch flags

typedef unsigned long long ull;

// ---------------- packed f32x2 helpers ----------------
__device__ __forceinline__ ull pk(float lo, float hi) {
    ull r;
    asm("mov.b64 %0, {%1, %2};" : "=l"(r) : "f"(lo), "f"(hi));
    return r;
}
__device__ __forceinline__ ull fma2(ull a, ull b, ull c) {
    ull d;
    asm("fma.rn.f32x2 %0, %1, %2, %3;" : "=l"(d) : "l"(a), "l"(b), "l"(c));
    return d;
}

// ---------------- barrier primitives ----------------
__device__ __forceinline__ unsigned int atom_add_acqrel(unsigned int* p, unsigned int v) {
    unsigned int old;
    asm volatile("atom.acq_rel.gpu.add.u32 %0, [%1], %2;"
                 : "=r"(old) : "l"(p), "r"(v) : "memory");
    return old;
}
__device__ __forceinline__ void st_release(unsigned int* p, unsigned int v) {
    asm volatile("st.release.gpu.u32 [%0], %1;" :: "l"(p), "r"(v) : "memory");
}
__device__ __forceinline__ unsigned int ld_acquire(unsigned int* p) {
    unsigned int v;
    asm volatile("ld.acquire.gpu.u32 %0, [%1];" : "=r"(v) : "l"(p) : "memory");
    return v;
}

// =====================================================================
// Phase 1: x_proj = inputs @ Wi, double-buffered smem pipeline
// =====================================================================
#define BM 128
#define BN 128
#define BKK 8

__global__ __launch_bounds__(256) void gemm_xproj(const float* __restrict__ A,
                                                  const float* __restrict__ Bw) {
    __shared__ float As[2][BKK][BM + 4];
    __shared__ float Bs[2][BKK][BN + 4];

    const int tid = threadIdx.x;
    const int m0 = blockIdx.y * BM;
    const int n0 = blockIdx.x * BN;
    const int tx = tid & 15;
    const int ty = tid >> 4;

    const int arow = tid >> 1;
    const int akq  = (tid & 1) * 4;
    const int bkr  = tid >> 5;
    const int bq   = tid & 31;

    ull acc[8][4];
#pragma unroll
    for (int i = 0; i < 8; i++)
#pragma unroll
        for (int j = 0; j < 4; j++) acc[i][j] = 0ull;

    // prologue: load tile 0
    {
        float4 av = *(const float4*)&A[(size_t)(m0 + arow) * D_ + akq];
        As[0][akq + 0][arow] = av.x;
        As[0][akq + 1][arow] = av.y;
        As[0][akq + 2][arow] = av.z;
        As[0][akq + 3][arow] = av.w;
        float4 bv = *(const float4*)&Bw[(size_t)bkr * G4_ + n0 + bq * 4];
        *(float4*)&Bs[0][bkr][bq * 4] = bv;
    }
    __syncthreads();

    int p = 0;
    for (int kt = 0; kt < D_ / BKK; ++kt) {
        float4 av, bv;
        const bool more = (kt + 1) < D_ / BKK;
        if (more) {
            av = *(const float4*)&A[(size_t)(m0 + arow) * D_ + (kt + 1) * BKK + akq];
            bv = *(const float4*)&Bw[(size_t)((kt + 1) * BKK + bkr) * G4_ + n0 + bq * 4];
        }

#pragma unroll
        for (int k = 0; k < BKK; ++k) {
            float4 a0 = *(const float4*)&As[p][k][ty * 8];
            float4 a1 = *(const float4*)&As[p][k][ty * 8 + 4];
            const ull* bp = (const ull*)&Bs[p][k][tx * 8];
            ull b0 = bp[0], b1 = bp[1], b2 = bp[2], b3 = bp[3];
            float ar[8] = {a0.x, a0.y, a0.z, a0.w, a1.x, a1.y, a1.z, a1.w};
#pragma unroll
            for (int i = 0; i < 8; i++) {
                ull a2 = pk(ar[i], ar[i]);
                acc[i][0] = fma2(a2, b0, acc[i][0]);
                acc[i][1] = fma2(a2, b1, acc[i][1]);
                acc[i][2] = fma2(a2, b2, acc[i][2]);
                acc[i][3] = fma2(a2, b3, acc[i][3]);
            }
        }

        if (more) {
            As[p ^ 1][akq + 0][arow] = av.x;
            As[p ^ 1][akq + 1][arow] = av.y;
            As[p ^ 1][akq + 2][arow] = av.z;
            As[p ^ 1][akq + 3][arow] = av.w;
            *(float4*)&Bs[p ^ 1][bkr][bq * 4] = bv;
        }
        __syncthreads();
        p ^= 1;
    }

#pragma unroll
    for (int i = 0; i < 8; i++) {
        size_t row = (size_t)(m0 + ty * 8 + i);
#pragma unroll
        for (int j = 0; j < 4; j++) {
            *(float2*)&g_xp[row * G4_ + n0 + tx * 8 + 2 * j] = *(float2*)&acc[i][j];
        }
    }
}

// =====================================================================
// Init
// =====================================================================
__global__ void init_kernel(const float* __restrict__ h0) {
    int i = blockIdx.x * blockDim.x + threadIdx.x;
    if (i < 4 * 32) { g_ctr4[i] = 0u; g_epoch4[i] = 0u; }
    if (i < B_ * H_) g_h[0][i] = h0[i];
}

// =====================================================================
// Phase 2 (v8 = v7 with fixed staging indices):
// register-resident weights + per-batch-group barriers + split staging.
// 128 blocks = 4 bgrp x 32 cg; block: 8 batches x 16 h-cols.
// 256 threads = 8 k-octants x 32 zc-pairs; thread: 2 z-cols, all 8 b.
// Half 0 stages k<256; half-1 LDG overlapped with segment-A fma.
// =====================================================================
#define HST 516
#define PST 68

__device__ __forceinline__ float sigf(float x) {
    return __fdividef(1.0f, 1.0f + __expf(-x));
}
__device__ __forceinline__ float tanhf_fast(float x) {
    return __fdividef(2.0f, 1.0f + __expf(-2.0f * x)) - 1.0f;
}

__global__ __launch_bounds__(256, 1) void lstm_seq(const float* __restrict__ c0,
                                                   const float* __restrict__ bias,
                                                   const float* __restrict__ Wh,
                                                   float* __restrict__ out) {
    __shared__ __align__(16) float h_s[8 * HST];
    __shared__ __align__(16) float part[64 * PST];
    __shared__ float z_s[64 * 9];
    __shared__ float c_s[8 * 16];
    __shared__ float b_s[64];

    const int tid = threadIdx.x;
    const int bl  = blockIdx.x;

    const int cg   = bl & 31;
    const int bgrp = bl >> 5;
    const int col0 = cg * 16;
    const int gb0  = bgrp * 8;

    unsigned int* ctr   = &g_ctr4[bgrp * 32];
    unsigned int* epoch = &g_epoch4[bgrp * 32];

    // ---- compute mapping ----
    const int zcp = tid & 31;
    const int ko  = tid >> 5;
    const int kA0 = ko * 32;          // segment A k-base (half 0)
    const int kB0 = 256 + ko * 32;    // segment B k-base (half 1)
    const int zct = 2 * zcp;

    // ---- staging decomposition (consistent for load AND store) ----
    const int s0b = tid >> 6;               // i = tid      : batch 0..3
    const int s0k = tid & 63;               //               k4 0..63
    const int s1b = 4 + s0b;                // i = tid+256  : batch 4..7

    // ---- reduce mapping ----
    const int rb   = tid >> 5;
    const int zc0r = 2 * (tid & 31);
    const int gzc0 = (zc0r >> 4) * H_ + col0 + (zc0r & 15);

    // ---- one-time: Wh slice -> registers ----
    ull wregA[2][16], wregB[2][16];
    {
        const int gcolA = (zct >> 4) * H_ + col0 + (zct & 15);
        const int gcolB = ((zct + 1) >> 4) * H_ + col0 + ((zct + 1) & 15);
#pragma unroll
        for (int kk = 0; kk < 32; kk += 2) {
            wregA[0][kk >> 1] = pk(Wh[(size_t)(kA0 + kk) * G4_ + gcolA],
                                   Wh[(size_t)(kA0 + kk + 1) * G4_ + gcolA]);
            wregA[1][kk >> 1] = pk(Wh[(size_t)(kA0 + kk) * G4_ + gcolB],
                                   Wh[(size_t)(kA0 + kk + 1) * G4_ + gcolB]);
            wregB[0][kk >> 1] = pk(Wh[(size_t)(kB0 + kk) * G4_ + gcolA],
                                   Wh[(size_t)(kB0 + kk + 1) * G4_ + gcolA]);
            wregB[1][kk >> 1] = pk(Wh[(size_t)(kB0 + kk) * G4_ + gcolB],
                                   Wh[(size_t)(kB0 + kk + 1) * G4_ + gcolB]);
        }
    }
    if (tid < 64) b_s[tid] = bias[(tid >> 4) * H_ + col0 + (tid & 15)];
    if (tid < 128) {
        int b = tid >> 4, j = tid & 15;
        c_s[b * 16 + j] = c0[(gb0 + b) * H_ + col0 + j];
    }
    __syncthreads();

    const float* xp_base = g_xp + (size_t)(gb0 + rb) * T_ * G4_ + gzc0;
    const float  bsz0 = b_s[zc0r];
    const float  bsz1 = b_s[zc0r + 1];

    int par = 0;
    for (int t = 0; t < T_; ++t) {
        const float4* hsrc4 = (const float4*)(g_h[par] + gb0 * H_);  // [8][128] float4

        // ---- stage half 0 (k4 in [0,64)) : 2 float4/thread ----
        float4 h0a = __ldcg(hsrc4 + s0b * 128 + s0k);
        float4 h0b = __ldcg(hsrc4 + s1b * 128 + s0k);
        float2 xpv = __ldcs((const float2*)(xp_base + (size_t)t * G4_));
        *(float4*)&h_s[s0b * HST + s0k * 4] = h0a;
        *(float4*)&h_s[s1b * HST + s0k * 4] = h0b;
        __syncthreads();

        // ---- issue half-1 loads (k4 in [64,128)); hidden by segment-A fma ----
        float4 h1a = __ldcg(hsrc4 + s0b * 128 + 64 + s0k);
        float4 h1b = __ldcg(hsrc4 + s1b * 128 + 64 + s0k);

        ull acc[2][8];
#pragma unroll
        for (int j = 0; j < 2; ++j)
#pragma unroll
            for (int bi = 0; bi < 8; ++bi) acc[j][bi] = 0ull;

        // ---- segment A: k in [kA0, kA0+32) ----
#pragma unroll 4
        for (int kk = 0; kk < 32; kk += 4) {
            ull w0a = wregA[0][kk >> 1], w0b = wregA[0][(kk >> 1) + 1];
            ull w1a = wregA[1][kk >> 1], w1b = wregA[1][(kk >> 1) + 1];
#pragma unroll
            for (int bi = 0; bi < 8; ++bi) {
                float4 hv = *(const float4*)&h_s[bi * HST + kA0 + kk];
                ull h01 = ((const ull*)&hv)[0], h23 = ((const ull*)&hv)[1];
                acc[0][bi] = fma2(h01, w0a, acc[0][bi]);
                acc[0][bi] = fma2(h23, w0b, acc[0][bi]);
                acc[1][bi] = fma2(h01, w1a, acc[1][bi]);
                acc[1][bi] = fma2(h23, w1b, acc[1][bi]);
            }
        }

        // ---- store half 1 into smem, sync ----
        *(float4*)&h_s[s0b * HST + (64 + s0k) * 4] = h1a;
        *(float4*)&h_s[s1b * HST + (64 + s0k) * 4] = h1b;
        __syncthreads();

        // ---- segment B: k in [kB0, kB0+32) ----
#pragma unroll 4
        for (int kk = 0; kk < 32; kk += 4) {
            ull w0a = wregB[0][kk >> 1], w0b = wregB[0][(kk >> 1) + 1];
            ull w1a = wregB[1][kk >> 1], w1b = wregB[1][(kk >> 1) + 1];
#pragma unroll
            for (int bi = 0; bi < 8; ++bi) {
                float4 hv = *(const float4*)&h_s[bi * HST + kB0 + kk];
                ull h01 = ((const ull*)&hv)[0], h23 = ((const ull*)&hv)[1];
                acc[0][bi] = fma2(h01, w0a, acc[0][bi]);
                acc[0][bi] = fma2(h23, w0b, acc[0][bi]);
                acc[1][bi] = fma2(h01, w1a, acc[1][bi]);
                acc[1][bi] = fma2(h23, w1b, acc[1][bi]);
            }
        }

        // ---- hadd over k-parity, stash partials ----
#pragma unroll
        for (int bi = 0; bi < 8; ++bi) {
            float2 pr;
            float2 a0 = *(float2*)&acc[0][bi];
            float2 a1 = *(float2*)&acc[1][bi];
            pr.x = a0.x + a0.y;
            pr.y = a1.x + a1.y;
            *(float2*)&part[(ko * 8 + bi) * PST + zct] = pr;
        }
        __syncthreads();

        // ---- reduce 8 k-octants + xp + bias -> z ----
        {
            float s0 = bsz0 + xpv.x;
            float s1 = bsz1 + xpv.y;
#pragma unroll
            for (int o = 0; o < 8; ++o) {
                float2 pv = *(const float2*)&part[(o * 8 + rb) * PST + zc0r];
                s0 += pv.x;
                s1 += pv.y;
            }
            z_s[zc0r * 9 + rb]       = s0;
            z_s[(zc0r + 1) * 9 + rb] = s1;
        }
        __syncthreads();

        // ---- gates: 128 threads = 8 b x 16 cols ----
        if (tid < 128) {
            int b = tid >> 4, j = tid & 15;
            float zi = z_s[j * 9 + b];
            float zf = z_s[(16 + j) * 9 + b];
            float zg = z_s[(32 + j) * 9 + b];
            float zo = z_s[(48 + j) * 9 + b];
            float cn = sigf(zf) * c_s[b * 16 + j] + sigf(zi) * tanhf_fast(zg);
            float hn = sigf(zo) * tanhf_fast(cn);
            c_s[b * 16 + j] = cn;
            g_h[par ^ 1][(gb0 + b) * H_ + col0 + j] = hn;
            __stcs(&out[((size_t)(gb0 + b) * T_ + t) * H_ + col0 + j], hn);
        }
        __syncthreads();

        // ---- per-batch-group barrier (32 arrivals, epoch flag) ----
        if (tid == 0) {
            unsigned int old = atom_add_acqrel(ctr, 1u);
            if (old == (unsigned int)t * 32u + 31u) {
                st_release(epoch, (unsigned int)(t + 1));   // last arriver
            } else {
                while (ld_acquire(epoch) < (unsigned int)(t + 1)) { }
            }
        }
        __syncthreads();
        par ^= 1;
    }
}

// =====================================================================
// launch
// =====================================================================
extern "C" void kernel_launch(void* const* d_in, const int* in_sizes, int n_in,
                              void* d_out, int out_size) {
    const float* inputs = (const float*)d_in[0];
    // d_in[1] = input_paddings (unused: all tokens valid)
    const float* c0   = (const float*)d_in[2];
    const float* h0   = (const float*)d_in[3];
    const float* Wi   = (const float*)d_in[4];
    const float* Wh   = (const float*)d_in[5];
    const float* bias = (const float*)d_in[6];
    float* out = (float*)d_out;

    dim3 g1(G4_ / BN, (B_ * T_) / BM);   // 16 x 512
    gemm_xproj<<<g1, 256>>>(inputs, Wi);
    init_kernel<<<64, 256>>>(h0);
    lstm_seq<<<128, 256>>>(c0, bias, Wh, out);
}